// round 1
// baseline (speedup 1.0000x reference)
#include <cuda_runtime.h>

#define BATCH   8
#define NPTS    4096
#define NPOINTS 1024
#define NSAMPLE 32
#define PIN_A   68    // padded row for 67-ch buffer (pad % 32 == 4 -> conflict-free)
#define PIN_B   132   // padded row for 128-ch buffer

// scratch (allocation-free rule: __device__ globals)
__device__ int g_group_idx[BATCH * NPOINTS * NSAMPLE];

// Non-FMA squared distance matching XLA's unfused mul/add reduce ((d0^2+d1^2)+d2^2)
__device__ __forceinline__ float sqd_nofma(float x, float y, float z,
                                           float cx, float cy, float cz) {
    float dx = x - cx, dy = y - cy, dz = z - cz;
    return __fadd_rn(__fadd_rn(__fmul_rn(dx, dx), __fmul_rn(dy, dy)), __fmul_rn(dz, dz));
}

// ---------------------------------------------------------------------------
// Kernel 1: farthest point sampling. One block per batch, 1024 threads,
// 4 points per thread held in registers. Writes new_xyz directly.
// ---------------------------------------------------------------------------
__global__ __launch_bounds__(1024) void fps_kernel(const float* __restrict__ xyz,
                                                   float* __restrict__ new_xyz) {
    const int b   = blockIdx.x;
    const int tid = threadIdx.x;
    const float* base = xyz + (size_t)b * NPTS * 3;

    float px[4], py[4], pz[4], pd[4];
    int   pn[4];
#pragma unroll
    for (int p = 0; p < 4; ++p) {
        int n = tid + p * 1024;
        pn[p] = n;
        px[p] = base[n * 3 + 0];
        py[p] = base[n * 3 + 1];
        pz[p] = base[n * 3 + 2];
        pd[p] = 1e10f;
    }

    __shared__ float sD[32], sX[32], sY[32], sZ[32];
    __shared__ int   sI[32];
    __shared__ float sCent[3];

    if (tid == 0) {
        sCent[0] = base[0];
        sCent[1] = base[1];
        sCent[2] = base[2];
        float* o = new_xyz + (size_t)b * NPOINTS * 3;
        o[0] = base[0]; o[1] = base[1]; o[2] = base[2];
    }
    __syncthreads();

    for (int t = 1; t < NPOINTS; ++t) {
        const float cx = sCent[0], cy = sCent[1], cz = sCent[2];

        float bd = -1.0f, bx = 0.f, by = 0.f, bz = 0.f;
        int   bi = 0x7fffffff;
#pragma unroll
        for (int p = 0; p < 4; ++p) {
            float d = sqd_nofma(px[p], py[p], pz[p], cx, cy, cz);
            pd[p] = fminf(pd[p], d);
            if (pd[p] > bd || (pd[p] == bd && pn[p] < bi)) {
                bd = pd[p]; bi = pn[p]; bx = px[p]; by = py[p]; bz = pz[p];
            }
        }
        // warp argmax reduce (tie-break: lowest index, matching jnp.argmax)
#pragma unroll
        for (int o = 16; o; o >>= 1) {
            float od = __shfl_xor_sync(0xffffffffu, bd, o);
            int   oi = __shfl_xor_sync(0xffffffffu, bi, o);
            float ox = __shfl_xor_sync(0xffffffffu, bx, o);
            float oy = __shfl_xor_sync(0xffffffffu, by, o);
            float oz = __shfl_xor_sync(0xffffffffu, bz, o);
            if (od > bd || (od == bd && oi < bi)) {
                bd = od; bi = oi; bx = ox; by = oy; bz = oz;
            }
        }
        if ((tid & 31) == 0) {
            int w = tid >> 5;
            sD[w] = bd; sI[w] = bi; sX[w] = bx; sY[w] = by; sZ[w] = bz;
        }
        __syncthreads();
        if (tid < 32) {
            bd = sD[tid]; bi = sI[tid]; bx = sX[tid]; by = sY[tid]; bz = sZ[tid];
#pragma unroll
            for (int o = 16; o; o >>= 1) {
                float od = __shfl_xor_sync(0xffffffffu, bd, o);
                int   oi = __shfl_xor_sync(0xffffffffu, bi, o);
                float ox = __shfl_xor_sync(0xffffffffu, bx, o);
                float oy = __shfl_xor_sync(0xffffffffu, by, o);
                float oz = __shfl_xor_sync(0xffffffffu, bz, o);
                if (od > bd || (od == bd && oi < bi)) {
                    bd = od; bi = oi; bx = ox; by = oy; bz = oz;
                }
            }
            if (tid == 0) {
                sCent[0] = bx; sCent[1] = by; sCent[2] = bz;
                float* o = new_xyz + ((size_t)b * NPOINTS + t) * 3;
                o[0] = bx; o[1] = by; o[2] = bz;
            }
        }
        __syncthreads();
    }
}

// ---------------------------------------------------------------------------
// Kernel 2: ball query. Grid (S/8, B), 256 threads: 8 warps = 8 query points.
// Picks the FIRST 32 indices (ascending) with d^2 <= r^2; pads with first.
// ---------------------------------------------------------------------------
__global__ __launch_bounds__(256) void ball_kernel(const float* __restrict__ xyz,
                                                   const float* __restrict__ new_xyz) {
    extern __shared__ float sxyz[];  // 4096*3 floats = 48 KB
    const int b = blockIdx.y;
    const float* base = xyz + (size_t)b * NPTS * 3;
    for (int i = threadIdx.x; i < NPTS * 3 / 4; i += 256)
        ((float4*)sxyz)[i] = ((const float4*)base)[i];
    __syncthreads();

    const int warp = threadIdx.x >> 5;
    const int lane = threadIdx.x & 31;
    const int s    = blockIdx.x * 8 + warp;

    const float* c = new_xyz + ((size_t)b * NPOINTS + s) * 3;
    const float cx = c[0], cy = c[1], cz = c[2];
    const float R2 = (float)(0.2 * 0.2);  // f64 square -> f32, matches XLA weak-type

    int* out  = g_group_idx + ((size_t)(b * NPOINTS + s)) * NSAMPLE;
    int cnt = 0, first = -1;
    for (int r = 0; r < NPTS / 32; ++r) {
        int n = r * 32 + lane;
        float d = sqd_nofma(sxyz[n * 3], sxyz[n * 3 + 1], sxyz[n * 3 + 2], cx, cy, cz);
        bool ok = !(d > R2);
        unsigned m = __ballot_sync(0xffffffffu, ok);
        if (first < 0 && m) first = r * 32 + (__ffs(m) - 1);
        if (ok) {
            int pos = cnt + __popc(m & ((1u << lane) - 1u));
            if (pos < NSAMPLE) out[pos] = n;
        }
        cnt += __popc(m);
        if (cnt >= NSAMPLE) break;
    }
    if (cnt < NSAMPLE && lane >= cnt && lane < NSAMPLE) out[lane] = first;
}

// ---------------------------------------------------------------------------
// Kernel 3: gather + (67->64 LN ReLU)(64->64 LN ReLU)(64->128 LN ReLU) + max.
// One block per (b,s): 128 threads, activations in smem, weights via __ldg
// (uniform broadcast, L1-resident).
// ---------------------------------------------------------------------------
template <int CIN, int COUT, int PIN, int POUT>
__device__ __forceinline__ void gemm_tile(const float* in_s,
                                          const float* __restrict__ W,
                                          const float* __restrict__ bias,
                                          float* out_s, int tid) {
    const int r = tid & 7;    // sample base: samples r, r+8, r+16, r+24
    const int c = tid >> 3;   // 0..15 output-column group
    constexpr int JW = COUT / 16;
    float acc[4][JW];
#pragma unroll
    for (int m = 0; m < 4; ++m)
#pragma unroll
        for (int j = 0; j < JW; ++j) acc[m][j] = 0.0f;

    const float* wbase = W + c * JW;
#pragma unroll 4
    for (int i = 0; i < CIN; ++i) {
        float a0 = in_s[(r + 0)  * PIN + i];
        float a1 = in_s[(r + 8)  * PIN + i];
        float a2 = in_s[(r + 16) * PIN + i];
        float a3 = in_s[(r + 24) * PIN + i];
        const float4* wp = (const float4*)(wbase + i * COUT);
#pragma unroll
        for (int v = 0; v < JW / 4; ++v) {
            float4 w = __ldg(wp + v);
            acc[0][v * 4 + 0] = fmaf(a0, w.x, acc[0][v * 4 + 0]);
            acc[0][v * 4 + 1] = fmaf(a0, w.y, acc[0][v * 4 + 1]);
            acc[0][v * 4 + 2] = fmaf(a0, w.z, acc[0][v * 4 + 2]);
            acc[0][v * 4 + 3] = fmaf(a0, w.w, acc[0][v * 4 + 3]);
            acc[1][v * 4 + 0] = fmaf(a1, w.x, acc[1][v * 4 + 0]);
            acc[1][v * 4 + 1] = fmaf(a1, w.y, acc[1][v * 4 + 1]);
            acc[1][v * 4 + 2] = fmaf(a1, w.z, acc[1][v * 4 + 2]);
            acc[1][v * 4 + 3] = fmaf(a1, w.w, acc[1][v * 4 + 3]);
            acc[2][v * 4 + 0] = fmaf(a2, w.x, acc[2][v * 4 + 0]);
            acc[2][v * 4 + 1] = fmaf(a2, w.y, acc[2][v * 4 + 1]);
            acc[2][v * 4 + 2] = fmaf(a2, w.z, acc[2][v * 4 + 2]);
            acc[2][v * 4 + 3] = fmaf(a2, w.w, acc[2][v * 4 + 3]);
            acc[3][v * 4 + 0] = fmaf(a3, w.x, acc[3][v * 4 + 0]);
            acc[3][v * 4 + 1] = fmaf(a3, w.y, acc[3][v * 4 + 1]);
            acc[3][v * 4 + 2] = fmaf(a3, w.z, acc[3][v * 4 + 2]);
            acc[3][v * 4 + 3] = fmaf(a3, w.w, acc[3][v * 4 + 3]);
        }
    }
#pragma unroll
    for (int j = 0; j < JW; ++j) {
        float bj = __ldg(bias + c * JW + j);
#pragma unroll
        for (int m = 0; m < 4; ++m)
            out_s[(r + 8 * m) * POUT + c * JW + j] = acc[m][j] + bj;
    }
}

template <int C, int P>
__device__ __forceinline__ void ln_relu(float* buf,
                                        const float* __restrict__ g,
                                        const float* __restrict__ be, int tid) {
    const int s = tid >> 2, q = tid & 3;  // 4 threads per sample (quad-aligned lanes)
    constexpr int SPAN = C / 4;
    float* row = buf + s * P + q * SPAN;
    float vals[SPAN];
    float sum = 0.0f;
#pragma unroll
    for (int j = 0; j < SPAN; ++j) { vals[j] = row[j]; sum += vals[j]; }
    sum += __shfl_xor_sync(0xffffffffu, sum, 1);
    sum += __shfl_xor_sync(0xffffffffu, sum, 2);
    const float mu = sum * (1.0f / C);  // 1/C exact power of two
    float sq = 0.0f;
#pragma unroll
    for (int j = 0; j < SPAN; ++j) { float d = vals[j] - mu; sq += d * d; }
    sq += __shfl_xor_sync(0xffffffffu, sq, 1);
    sq += __shfl_xor_sync(0xffffffffu, sq, 2);
    const float inv = rsqrtf(sq * (1.0f / C) + 1e-5f);
#pragma unroll
    for (int j = 0; j < SPAN; ++j) {
        int jj = q * SPAN + j;
        float v = (vals[j] - mu) * inv * __ldg(g + jj) + __ldg(be + jj);
        row[j] = fmaxf(v, 0.0f);
    }
}

__global__ __launch_bounds__(128) void mlp_kernel(
    const float* __restrict__ xyz, const float* __restrict__ points,
    const float* __restrict__ new_xyz,
    const float* __restrict__ W1, const float* __restrict__ b1,
    const float* __restrict__ g1, const float* __restrict__ be1,
    const float* __restrict__ W2, const float* __restrict__ b2,
    const float* __restrict__ g2, const float* __restrict__ be2,
    const float* __restrict__ W3, const float* __restrict__ b3,
    const float* __restrict__ g3, const float* __restrict__ be3,
    float* __restrict__ new_points) {
    __shared__ float bufA[32 * PIN_A];
    __shared__ float bufB[32 * PIN_B];
    __shared__ int   sIdx[32];
    __shared__ float sCen[3];

    const int pair = blockIdx.x;        // b*1024 + s
    const int b    = pair >> 10;
    const int tid  = threadIdx.x;

    if (tid < 32) sIdx[tid] = g_group_idx[pair * NSAMPLE + tid];
    if (tid < 3)  sCen[tid] = new_xyz[(size_t)pair * 3 + tid];
    __syncthreads();

    // gather: 4 threads per sample; 67 channels = [xyz-offset(3), points(64)]
    {
        const int k = tid >> 2, q = tid & 3;
        const int n = sIdx[k];
        const float4* prow = (const float4*)(points + ((size_t)b * NPTS + n) * 64) + q * 4;
        float* dst = bufA + k * PIN_A + 3 + q * 16;
#pragma unroll
        for (int v = 0; v < 4; ++v) {
            float4 f = __ldg(prow + v);
            dst[v * 4 + 0] = f.x;
            dst[v * 4 + 1] = f.y;
            dst[v * 4 + 2] = f.z;
            dst[v * 4 + 3] = f.w;
        }
        if (q == 0) {
            const float* xr = xyz + ((size_t)b * NPTS + n) * 3;
            bufA[k * PIN_A + 0] = xr[0] - sCen[0];
            bufA[k * PIN_A + 1] = xr[1] - sCen[1];
            bufA[k * PIN_A + 2] = xr[2] - sCen[2];
        }
    }
    __syncthreads();

    gemm_tile<67, 64, PIN_A, PIN_B>(bufA, W1, b1, bufB, tid);
    __syncthreads();
    ln_relu<64, PIN_B>(bufB, g1, be1, tid);
    __syncthreads();

    gemm_tile<64, 64, PIN_B, PIN_A>(bufB, W2, b2, bufA, tid);
    __syncthreads();
    ln_relu<64, PIN_A>(bufA, g2, be2, tid);
    __syncthreads();

    gemm_tile<64, 128, PIN_A, PIN_B>(bufA, W3, b3, bufB, tid);
    __syncthreads();
    ln_relu<128, PIN_B>(bufB, g3, be3, tid);
    __syncthreads();

    // max over the 32 group samples; relu outputs are >= 0 so init 0 is exact
    {
        const int j = tid;  // 0..127
        float m = 0.0f;
#pragma unroll 8
        for (int k = 0; k < 32; ++k) m = fmaxf(m, bufB[k * PIN_B + j]);
        new_points[(size_t)pair * 128 + j] = m;
    }
}

// ---------------------------------------------------------------------------
extern "C" void kernel_launch(void* const* d_in, const int* in_sizes, int n_in,
                              void* d_out, int out_size) {
    (void)in_sizes; (void)n_in; (void)out_size;
    const float* xyz    = (const float*)d_in[0];
    const float* points = (const float*)d_in[1];
    const float* W1  = (const float*)d_in[2];
    const float* b1  = (const float*)d_in[3];
    const float* g1  = (const float*)d_in[4];
    const float* be1 = (const float*)d_in[5];
    const float* W2  = (const float*)d_in[6];
    const float* b2  = (const float*)d_in[7];
    const float* g2  = (const float*)d_in[8];
    const float* be2 = (const float*)d_in[9];
    const float* W3  = (const float*)d_in[10];
    const float* b3  = (const float*)d_in[11];
    const float* g3  = (const float*)d_in[12];
    const float* be3 = (const float*)d_in[13];

    float* out        = (float*)d_out;
    float* new_xyz    = out;                          // [8,1024,3]
    float* new_points = out + BATCH * NPOINTS * 3;    // [8,1024,128]

    fps_kernel<<<BATCH, 1024>>>(xyz, new_xyz);
    ball_kernel<<<dim3(NPOINTS / 8, BATCH), 256, NPTS * 3 * sizeof(float)>>>(xyz, new_xyz);
    mlp_kernel<<<BATCH * NPOINTS, 128>>>(xyz, points, new_xyz,
                                         W1, b1, g1, be1,
                                         W2, b2, g2, be2,
                                         W3, b3, g3, be3,
                                         new_points);
}

// round 3
// speedup vs baseline: 1.3439x; 1.3439x over previous
#include <cuda_runtime.h>

#define BATCH   8
#define NPTS    4096
#define NPOINTS 1024
#define NSAMPLE 32
#define PIN_A   68    // padded row for 67-ch buffer
#define PIN_B   132   // padded row for 128-ch buffer

// scratch (allocation-free rule: __device__ globals)
__device__ int g_group_idx[BATCH * NPOINTS * NSAMPLE];

// Non-FMA squared distance matching XLA's unfused mul/add reduce ((d0^2+d1^2)+d2^2)
__device__ __forceinline__ float sqd_nofma(float x, float y, float z,
                                           float cx, float cy, float cz) {
    float dx = x - cx, dy = y - cy, dz = z - cz;
    return __fadd_rn(__fadd_rn(__fmul_rn(dx, dx), __fmul_rn(dy, dy)), __fmul_rn(dz, dz));
}

// ---------------------------------------------------------------------------
// Kernel 1: farthest point sampling. One block per batch, 1024 threads,
// 4 points per thread in registers. Argmax via packed u64 key:
//   key = (bits(dist) << 32) | (4095 - idx)
// dist >= 0 so float order == unsigned bit order; tie -> larger (4095-idx)
// -> smaller idx, matching jnp.argmax. One barrier per step via 3-slot
// rotating shared atomicMax target.
// ---------------------------------------------------------------------------
__global__ __launch_bounds__(1024) void fps_kernel(const float* __restrict__ xyz,
                                                   float* __restrict__ new_xyz) {
    const int b   = blockIdx.x;
    const int tid = threadIdx.x;
    const float* base = xyz + (size_t)b * NPTS * 3;

    float px[4], py[4], pz[4], pd[4];
    int   pn[4];
#pragma unroll
    for (int p = 0; p < 4; ++p) {
        int n = tid + p * 1024;
        pn[p] = n;
        px[p] = base[n * 3 + 0];
        py[p] = base[n * 3 + 1];
        pz[p] = base[n * 3 + 2];
        pd[p] = 1e10f;
    }

    __shared__ unsigned long long sKey[3];

    float cx = __ldg(base + 0), cy = __ldg(base + 1), cz = __ldg(base + 2);
    if (tid == 0) {
        sKey[0] = 0ull; sKey[1] = 0ull; sKey[2] = 0ull;
        float* o = new_xyz + (size_t)b * NPOINTS * 3;
        o[0] = cx; o[1] = cy; o[2] = cz;
    }
    __syncthreads();

    int slot = 1, nslot = 2;  // slot = t % 3 starting at t=1
    for (int t = 1; t < NPOINTS; ++t) {
        unsigned long long best = 0ull;
#pragma unroll
        for (int p = 0; p < 4; ++p) {
            float d = sqd_nofma(px[p], py[p], pz[p], cx, cy, cz);
            pd[p] = fminf(pd[p], d);
            unsigned long long key =
                ((unsigned long long)__float_as_uint(pd[p]) << 32) |
                (unsigned long long)(unsigned)(4095 - pn[p]);
            best = (key > best) ? key : best;
        }
#pragma unroll
        for (int o = 16; o; o >>= 1) {
            unsigned long long ok = __shfl_xor_sync(0xffffffffu, best, o);
            best = (ok > best) ? ok : best;
        }
        if ((tid & 31) == 0) atomicMax(&sKey[slot], best);
        if (tid == 0) sKey[nslot] = 0ull;  // reset one barrier ahead (safe: 3-slot rotation)
        __syncthreads();

        unsigned long long win = sKey[slot];
        int idx = 4095 - (int)(unsigned)(win & 0xffffffffull);
        cx = __ldg(base + idx * 3 + 0);   // uniform broadcast, L1-resident
        cy = __ldg(base + idx * 3 + 1);
        cz = __ldg(base + idx * 3 + 2);
        if (tid == 0) {
            float* o = new_xyz + ((size_t)b * NPOINTS + t) * 3;
            o[0] = cx; o[1] = cy; o[2] = cz;
        }
        slot = nslot;
        nslot = nslot + 1; if (nslot == 3) nslot = 0;
    }
}

// ---------------------------------------------------------------------------
// Kernel 2: ball query. Grid (S/8, B), 256 threads: 8 warps = 8 query points.
// ---------------------------------------------------------------------------
__global__ __launch_bounds__(256) void ball_kernel(const float* __restrict__ xyz,
                                                   const float* __restrict__ new_xyz) {
    extern __shared__ float sxyz[];  // 4096*3 floats = 48 KB
    const int b = blockIdx.y;
    const float* base = xyz + (size_t)b * NPTS * 3;
    for (int i = threadIdx.x; i < NPTS * 3 / 4; i += 256)
        ((float4*)sxyz)[i] = ((const float4*)base)[i];
    __syncthreads();

    const int warp = threadIdx.x >> 5;
    const int lane = threadIdx.x & 31;
    const int s    = blockIdx.x * 8 + warp;

    const float* c = new_xyz + ((size_t)b * NPOINTS + s) * 3;
    const float cx = c[0], cy = c[1], cz = c[2];
    const float R2 = (float)(0.2 * 0.2);

    int* out  = g_group_idx + ((size_t)(b * NPOINTS + s)) * NSAMPLE;
    int cnt = 0, first = -1;
    for (int r = 0; r < NPTS / 32; ++r) {
        int n = r * 32 + lane;
        float d = sqd_nofma(sxyz[n * 3], sxyz[n * 3 + 1], sxyz[n * 3 + 2], cx, cy, cz);
        bool ok = !(d > R2);
        unsigned m = __ballot_sync(0xffffffffu, ok);
        if (first < 0 && m) first = r * 32 + (__ffs(m) - 1);
        if (ok) {
            int pos = cnt + __popc(m & ((1u << lane) - 1u));
            if (pos < NSAMPLE) out[pos] = n;
        }
        cnt += __popc(m);
        if (cnt >= NSAMPLE) break;
    }
    if (cnt < NSAMPLE && lane >= cnt && lane < NSAMPLE) out[lane] = first;
}

// ---------------------------------------------------------------------------
// Kernel 3: gather + MLP(67->64->64->128, LN+ReLU each) + max over samples.
// K-loop vectorized by 4: float4 LDS for activations, float4 LDG for weights.
// ---------------------------------------------------------------------------
template <int CIN, int COUT, int PIN, int POUT>
__device__ __forceinline__ void gemm_tile(const float* in_s,
                                          const float* __restrict__ W,
                                          const float* __restrict__ bias,
                                          float* out_s, int tid) {
    const int r = tid & 7;    // samples r, r+8, r+16, r+24
    const int c = tid >> 3;   // output column group 0..15
    constexpr int JW = COUT / 16;
    float acc[4][JW];
#pragma unroll
    for (int m = 0; m < 4; ++m)
#pragma unroll
        for (int j = 0; j < JW; ++j) acc[m][j] = 0.0f;

    const float* wbase = W + c * JW;
    constexpr int CMAIN = CIN & ~3;

    for (int i = 0; i < CMAIN; i += 4) {
        float4 a0 = *(const float4*)(in_s + (r + 0)  * PIN + i);
        float4 a1 = *(const float4*)(in_s + (r + 8)  * PIN + i);
        float4 a2 = *(const float4*)(in_s + (r + 16) * PIN + i);
        float4 a3 = *(const float4*)(in_s + (r + 24) * PIN + i);
        const float av[4][4] = {
            {a0.x, a1.x, a2.x, a3.x},
            {a0.y, a1.y, a2.y, a3.y},
            {a0.z, a1.z, a2.z, a3.z},
            {a0.w, a1.w, a2.w, a3.w}};
#pragma unroll
        for (int u = 0; u < 4; ++u) {
            const float4* wp = (const float4*)(wbase + (i + u) * COUT);
#pragma unroll
            for (int v = 0; v < JW / 4; ++v) {
                float4 w = __ldg(wp + v);
#pragma unroll
                for (int m = 0; m < 4; ++m) {
                    acc[m][v * 4 + 0] = fmaf(av[u][m], w.x, acc[m][v * 4 + 0]);
                    acc[m][v * 4 + 1] = fmaf(av[u][m], w.y, acc[m][v * 4 + 1]);
                    acc[m][v * 4 + 2] = fmaf(av[u][m], w.z, acc[m][v * 4 + 2]);
                    acc[m][v * 4 + 3] = fmaf(av[u][m], w.w, acc[m][v * 4 + 3]);
                }
            }
        }
    }
    // remainder channels (layer 1: i = 64..66)
    for (int i = CMAIN; i < CIN; ++i) {
        float s0 = in_s[(r + 0)  * PIN + i];
        float s1 = in_s[(r + 8)  * PIN + i];
        float s2 = in_s[(r + 16) * PIN + i];
        float s3 = in_s[(r + 24) * PIN + i];
        const float4* wp = (const float4*)(wbase + i * COUT);
#pragma unroll
        for (int v = 0; v < JW / 4; ++v) {
            float4 w = __ldg(wp + v);
            acc[0][v * 4 + 0] = fmaf(s0, w.x, acc[0][v * 4 + 0]);
            acc[0][v * 4 + 1] = fmaf(s0, w.y, acc[0][v * 4 + 1]);
            acc[0][v * 4 + 2] = fmaf(s0, w.z, acc[0][v * 4 + 2]);
            acc[0][v * 4 + 3] = fmaf(s0, w.w, acc[0][v * 4 + 3]);
            acc[1][v * 4 + 0] = fmaf(s1, w.x, acc[1][v * 4 + 0]);
            acc[1][v * 4 + 1] = fmaf(s1, w.y, acc[1][v * 4 + 1]);
            acc[1][v * 4 + 2] = fmaf(s1, w.z, acc[1][v * 4 + 2]);
            acc[1][v * 4 + 3] = fmaf(s1, w.w, acc[1][v * 4 + 3]);
            acc[2][v * 4 + 0] = fmaf(s2, w.x, acc[2][v * 4 + 0]);
            acc[2][v * 4 + 1] = fmaf(s2, w.y, acc[2][v * 4 + 1]);
            acc[2][v * 4 + 2] = fmaf(s2, w.z, acc[2][v * 4 + 2]);
            acc[2][v * 4 + 3] = fmaf(s2, w.w, acc[2][v * 4 + 3]);
            acc[3][v * 4 + 0] = fmaf(s3, w.x, acc[3][v * 4 + 0]);
            acc[3][v * 4 + 1] = fmaf(s3, w.y, acc[3][v * 4 + 1]);
            acc[3][v * 4 + 2] = fmaf(s3, w.z, acc[3][v * 4 + 2]);
            acc[3][v * 4 + 3] = fmaf(s3, w.w, acc[3][v * 4 + 3]);
        }
    }
#pragma unroll
    for (int j = 0; j < JW; ++j) {
        float bj = __ldg(bias + c * JW + j);
#pragma unroll
        for (int m = 0; m < 4; ++m)
            out_s[(r + 8 * m) * POUT + c * JW + j] = acc[m][j] + bj;
    }
}

template <int C, int P>
__device__ __forceinline__ void ln_relu(float* buf,
                                        const float* __restrict__ g,
                                        const float* __restrict__ be, int tid) {
    const int s = tid >> 2, q = tid & 3;  // 4 threads per sample
    constexpr int SPAN = C / 4;
    float* row = buf + s * P + q * SPAN;
    float vals[SPAN];
    float sum = 0.0f;
#pragma unroll
    for (int j = 0; j < SPAN; ++j) { vals[j] = row[j]; sum += vals[j]; }
    sum += __shfl_xor_sync(0xffffffffu, sum, 1);
    sum += __shfl_xor_sync(0xffffffffu, sum, 2);
    const float mu = sum * (1.0f / C);
    float sq = 0.0f;
#pragma unroll
    for (int j = 0; j < SPAN; ++j) { float d = vals[j] - mu; sq += d * d; }
    sq += __shfl_xor_sync(0xffffffffu, sq, 1);
    sq += __shfl_xor_sync(0xffffffffu, sq, 2);
    const float inv = rsqrtf(sq * (1.0f / C) + 1e-5f);
#pragma unroll
    for (int j = 0; j < SPAN; ++j) {
        int jj = q * SPAN + j;
        float v = (vals[j] - mu) * inv * __ldg(g + jj) + __ldg(be + jj);
        row[j] = fmaxf(v, 0.0f);
    }
}

__global__ __launch_bounds__(128) void mlp_kernel(
    const float* __restrict__ xyz, const float* __restrict__ points,
    const float* __restrict__ new_xyz,
    const float* __restrict__ W1, const float* __restrict__ b1,
    const float* __restrict__ g1, const float* __restrict__ be1,
    const float* __restrict__ W2, const float* __restrict__ b2,
    const float* __restrict__ g2, const float* __restrict__ be2,
    const float* __restrict__ W3, const float* __restrict__ b3,
    const float* __restrict__ g3, const float* __restrict__ be3,
    float* __restrict__ new_points) {
    __shared__ float bufA[32 * PIN_A];
    __shared__ float bufB[32 * PIN_B];
    __shared__ int   sIdx[32];
    __shared__ float sCen[3];

    const int pair = blockIdx.x;        // b*1024 + s
    const int b    = pair >> 10;
    const int tid  = threadIdx.x;

    if (tid < 32) sIdx[tid] = g_group_idx[pair * NSAMPLE + tid];
    if (tid < 3)  sCen[tid] = new_xyz[(size_t)pair * 3 + tid];
    __syncthreads();

    // gather: 4 threads per sample; 67 channels = [xyz-offset(3), points(64)]
    {
        const int k = tid >> 2, q = tid & 3;
        const int n = sIdx[k];
        const float4* prow = (const float4*)(points + ((size_t)b * NPTS + n) * 64) + q * 4;
        float* dst = bufA + k * PIN_A + 3 + q * 16;
#pragma unroll
        for (int v = 0; v < 4; ++v) {
            float4 f = __ldg(prow + v);
            dst[v * 4 + 0] = f.x;
            dst[v * 4 + 1] = f.y;
            dst[v * 4 + 2] = f.z;
            dst[v * 4 + 3] = f.w;
        }
        if (q == 0) {
            const float* xr = xyz + ((size_t)b * NPTS + n) * 3;
            bufA[k * PIN_A + 0] = xr[0] - sCen[0];
            bufA[k * PIN_A + 1] = xr[1] - sCen[1];
            bufA[k * PIN_A + 2] = xr[2] - sCen[2];
        }
    }
    __syncthreads();

    gemm_tile<67, 64, PIN_A, PIN_B>(bufA, W1, b1, bufB, tid);
    __syncthreads();
    ln_relu<64, PIN_B>(bufB, g1, be1, tid);
    __syncthreads();

    gemm_tile<64, 64, PIN_B, PIN_A>(bufB, W2, b2, bufA, tid);
    __syncthreads();
    ln_relu<64, PIN_A>(bufA, g2, be2, tid);
    __syncthreads();

    gemm_tile<64, 128, PIN_A, PIN_B>(bufA, W3, b3, bufB, tid);
    __syncthreads();
    ln_relu<128, PIN_B>(bufB, g3, be3, tid);
    __syncthreads();

    // max over the 32 group samples; relu outputs >= 0 so init 0 is exact
    {
        const int j = tid;
        float m = 0.0f;
#pragma unroll 8
        for (int k = 0; k < 32; ++k) m = fmaxf(m, bufB[k * PIN_B + j]);
        new_points[(size_t)pair * 128 + j] = m;
    }
}

// ---------------------------------------------------------------------------
extern "C" void kernel_launch(void* const* d_in, const int* in_sizes, int n_in,
                              void* d_out, int out_size) {
    (void)in_sizes; (void)n_in; (void)out_size;
    const float* xyz    = (const float*)d_in[0];
    const float* points = (const float*)d_in[1];
    const float* W1  = (const float*)d_in[2];
    const float* b1  = (const float*)d_in[3];
    const float* g1  = (const float*)d_in[4];
    const float* be1 = (const float*)d_in[5];
    const float* W2  = (const float*)d_in[6];
    const float* b2  = (const float*)d_in[7];
    const float* g2  = (const float*)d_in[8];
    const float* be2 = (const float*)d_in[9];
    const float* W3  = (const float*)d_in[10];
    const float* b3  = (const float*)d_in[11];
    const float* g3  = (const float*)d_in[12];
    const float* be3 = (const float*)d_in[13];

    float* out        = (float*)d_out;
    float* new_xyz    = out;                          // [8,1024,3]
    float* new_points = out + BATCH * NPOINTS * 3;    // [8,1024,128]

    fps_kernel<<<BATCH, 1024>>>(xyz, new_xyz);
    ball_kernel<<<dim3(NPOINTS / 8, BATCH), 256, NPTS * 3 * sizeof(float)>>>(xyz, new_xyz);
    mlp_kernel<<<BATCH * NPOINTS, 128>>>(xyz, points, new_xyz,
                                         W1, b1, g1, be1,
                                         W2, b2, g2, be2,
                                         W3, b3, g3, be3,
                                         new_points);
}

// round 4
// speedup vs baseline: 1.6043x; 1.1937x over previous
#include <cuda_runtime.h>

#define BATCH   8
#define NPTS    4096
#define NPOINTS 1024
#define NSAMPLE 32
#define PIN_A   68    // padded row for 67-ch buffer
#define PIN_B   132   // padded row for 128-ch buffer

// scratch (allocation-free rule: __device__ globals)
__device__ int g_group_idx[BATCH * NPOINTS * NSAMPLE];

// Non-FMA squared distance matching XLA's unfused mul/add reduce ((d0^2+d1^2)+d2^2)
__device__ __forceinline__ float sqd_nofma(float x, float y, float z,
                                           float cx, float cy, float cz) {
    float dx = x - cx, dy = y - cy, dz = z - cz;
    return __fadd_rn(__fadd_rn(__fmul_rn(dx, dx), __fmul_rn(dy, dy)), __fmul_rn(dz, dz));
}

// ---------------------------------------------------------------------------
// Kernel 1: farthest point sampling. One block per batch, 256 threads,
// 16 points per thread in registers.
// Per step: per-thread best via strict > (indices ascend -> first-max = lowest
// index, matching jnp.argmax), pack u64 key (bits(dist)<<32 | (4095-idx)),
// 5-round warp shuffle max, leaders -> smem, warp0 3-round combine, uniform
// centroid LDG. No atomics (the R2 atomicMax tail serialized ~1000 cyc/step).
// ---------------------------------------------------------------------------
__global__ __launch_bounds__(256) void fps_kernel(const float* __restrict__ xyz,
                                                  float* __restrict__ new_xyz) {
    const int b   = blockIdx.x;
    const int tid = threadIdx.x;
    const float* base = xyz + (size_t)b * NPTS * 3;

    float px[16], py[16], pz[16], pd[16];
#pragma unroll
    for (int p = 0; p < 16; ++p) {
        int n = tid + p * 256;
        px[p] = base[n * 3 + 0];
        py[p] = base[n * 3 + 1];
        pz[p] = base[n * 3 + 2];
        pd[p] = 1e10f;
    }

    __shared__ unsigned long long sWarp[8];
    __shared__ float sCent[4];

    if (tid == 0) {
        sCent[0] = base[0]; sCent[1] = base[1]; sCent[2] = base[2];
        float* o = new_xyz + (size_t)b * NPOINTS * 3;
        o[0] = base[0]; o[1] = base[1]; o[2] = base[2];
    }
    __syncthreads();

    for (int t = 1; t < NPOINTS; ++t) {
        const float cx = sCent[0], cy = sCent[1], cz = sCent[2];

        float bd = -1.0f;
        int   bp = 0;
#pragma unroll
        for (int p = 0; p < 16; ++p) {
            float d = sqd_nofma(px[p], py[p], pz[p], cx, cy, cz);
            pd[p] = fminf(pd[p], d);
            if (pd[p] > bd) { bd = pd[p]; bp = p; }   // strict >: keeps lowest idx
        }
        const int bn = tid + bp * 256;
        unsigned long long key =
            ((unsigned long long)__float_as_uint(bd) << 32) |
            (unsigned long long)(unsigned)(4095 - bn);
#pragma unroll
        for (int o = 16; o; o >>= 1) {
            unsigned long long ok = __shfl_xor_sync(0xffffffffu, key, o);
            key = (ok > key) ? ok : key;
        }
        if ((tid & 31) == 0) sWarp[tid >> 5] = key;
        __syncthreads();

        if (tid < 32) {
            unsigned long long k = (tid < 8) ? sWarp[tid] : 0ull;
#pragma unroll
            for (int o = 4; o; o >>= 1) {
                unsigned long long ok = __shfl_xor_sync(0xffffffffu, k, o);
                k = (ok > k) ? ok : k;
            }
            if (tid == 0) {
                int idx = 4095 - (int)(unsigned)(k & 0xffffffffull);
                float x = __ldg(base + idx * 3 + 0);   // L1-resident after warmup
                float y = __ldg(base + idx * 3 + 1);
                float z = __ldg(base + idx * 3 + 2);
                sCent[0] = x; sCent[1] = y; sCent[2] = z;
                float* o = new_xyz + ((size_t)b * NPOINTS + t) * 3;
                o[0] = x; o[1] = y; o[2] = z;
            }
        }
        __syncthreads();
    }
}

// ---------------------------------------------------------------------------
// Kernel 2: ball query. Grid (S/8, B), 256 threads: 8 warps = 8 query points.
// ---------------------------------------------------------------------------
__global__ __launch_bounds__(256) void ball_kernel(const float* __restrict__ xyz,
                                                   const float* __restrict__ new_xyz) {
    extern __shared__ float sxyz[];  // 4096*3 floats = 48 KB
    const int b = blockIdx.y;
    const float* base = xyz + (size_t)b * NPTS * 3;
    for (int i = threadIdx.x; i < NPTS * 3 / 4; i += 256)
        ((float4*)sxyz)[i] = ((const float4*)base)[i];
    __syncthreads();

    const int warp = threadIdx.x >> 5;
    const int lane = threadIdx.x & 31;
    const int s    = blockIdx.x * 8 + warp;

    const float* c = new_xyz + ((size_t)b * NPOINTS + s) * 3;
    const float cx = c[0], cy = c[1], cz = c[2];
    const float R2 = (float)(0.2 * 0.2);

    int* out  = g_group_idx + ((size_t)(b * NPOINTS + s)) * NSAMPLE;
    int cnt = 0, first = -1;
    for (int r = 0; r < NPTS / 32; ++r) {
        int n = r * 32 + lane;
        float d = sqd_nofma(sxyz[n * 3], sxyz[n * 3 + 1], sxyz[n * 3 + 2], cx, cy, cz);
        bool ok = !(d > R2);
        unsigned m = __ballot_sync(0xffffffffu, ok);
        if (first < 0 && m) first = r * 32 + (__ffs(m) - 1);
        if (ok) {
            int pos = cnt + __popc(m & ((1u << lane) - 1u));
            if (pos < NSAMPLE) out[pos] = n;
        }
        cnt += __popc(m);
        if (cnt >= NSAMPLE) break;
    }
    if (cnt < NSAMPLE && lane >= cnt && lane < NSAMPLE) out[lane] = first;
}

// ---------------------------------------------------------------------------
// Kernel 3: gather + MLP(67->64->64->128, LN+ReLU each) + max over samples.
// ---------------------------------------------------------------------------
template <int CIN, int COUT, int PIN, int POUT>
__device__ __forceinline__ void gemm_tile(const float* in_s,
                                          const float* __restrict__ W,
                                          const float* __restrict__ bias,
                                          float* out_s, int tid) {
    const int r = tid & 7;    // samples r, r+8, r+16, r+24
    const int c = tid >> 3;   // output column group 0..15
    constexpr int JW = COUT / 16;
    float acc[4][JW];
#pragma unroll
    for (int m = 0; m < 4; ++m)
#pragma unroll
        for (int j = 0; j < JW; ++j) acc[m][j] = 0.0f;

    const float* wbase = W + c * JW;
    constexpr int CMAIN = CIN & ~3;

    for (int i = 0; i < CMAIN; i += 4) {
        float4 a0 = *(const float4*)(in_s + (r + 0)  * PIN + i);
        float4 a1 = *(const float4*)(in_s + (r + 8)  * PIN + i);
        float4 a2 = *(const float4*)(in_s + (r + 16) * PIN + i);
        float4 a3 = *(const float4*)(in_s + (r + 24) * PIN + i);
        const float av[4][4] = {
            {a0.x, a1.x, a2.x, a3.x},
            {a0.y, a1.y, a2.y, a3.y},
            {a0.z, a1.z, a2.z, a3.z},
            {a0.w, a1.w, a2.w, a3.w}};
#pragma unroll
        for (int u = 0; u < 4; ++u) {
            const float4* wp = (const float4*)(wbase + (i + u) * COUT);
#pragma unroll
            for (int v = 0; v < JW / 4; ++v) {
                float4 w = __ldg(wp + v);
#pragma unroll
                for (int m = 0; m < 4; ++m) {
                    acc[m][v * 4 + 0] = fmaf(av[u][m], w.x, acc[m][v * 4 + 0]);
                    acc[m][v * 4 + 1] = fmaf(av[u][m], w.y, acc[m][v * 4 + 1]);
                    acc[m][v * 4 + 2] = fmaf(av[u][m], w.z, acc[m][v * 4 + 2]);
                    acc[m][v * 4 + 3] = fmaf(av[u][m], w.w, acc[m][v * 4 + 3]);
                }
            }
        }
    }
    // remainder channels (layer 1: i = 64..66)
    for (int i = CMAIN; i < CIN; ++i) {
        float s0 = in_s[(r + 0)  * PIN + i];
        float s1 = in_s[(r + 8)  * PIN + i];
        float s2 = in_s[(r + 16) * PIN + i];
        float s3 = in_s[(r + 24) * PIN + i];
        const float4* wp = (const float4*)(wbase + i * COUT);
#pragma unroll
        for (int v = 0; v < JW / 4; ++v) {
            float4 w = __ldg(wp + v);
            acc[0][v * 4 + 0] = fmaf(s0, w.x, acc[0][v * 4 + 0]);
            acc[0][v * 4 + 1] = fmaf(s0, w.y, acc[0][v * 4 + 1]);
            acc[0][v * 4 + 2] = fmaf(s0, w.z, acc[0][v * 4 + 2]);
            acc[0][v * 4 + 3] = fmaf(s0, w.w, acc[0][v * 4 + 3]);
            acc[1][v * 4 + 0] = fmaf(s1, w.x, acc[1][v * 4 + 0]);
            acc[1][v * 4 + 1] = fmaf(s1, w.y, acc[1][v * 4 + 1]);
            acc[1][v * 4 + 2] = fmaf(s1, w.z, acc[1][v * 4 + 2]);
            acc[1][v * 4 + 3] = fmaf(s1, w.w, acc[1][v * 4 + 3]);
            acc[2][v * 4 + 0] = fmaf(s2, w.x, acc[2][v * 4 + 0]);
            acc[2][v * 4 + 1] = fmaf(s2, w.y, acc[2][v * 4 + 1]);
            acc[2][v * 4 + 2] = fmaf(s2, w.z, acc[2][v * 4 + 2]);
            acc[2][v * 4 + 3] = fmaf(s2, w.w, acc[2][v * 4 + 3]);
            acc[3][v * 4 + 0] = fmaf(s3, w.x, acc[3][v * 4 + 0]);
            acc[3][v * 4 + 1] = fmaf(s3, w.y, acc[3][v * 4 + 1]);
            acc[3][v * 4 + 2] = fmaf(s3, w.z, acc[3][v * 4 + 2]);
            acc[3][v * 4 + 3] = fmaf(s3, w.w, acc[3][v * 4 + 3]);
        }
    }
#pragma unroll
    for (int j = 0; j < JW; ++j) {
        float bj = __ldg(bias + c * JW + j);
#pragma unroll
        for (int m = 0; m < 4; ++m)
            out_s[(r + 8 * m) * POUT + c * JW + j] = acc[m][j] + bj;
    }
}

template <int C, int P>
__device__ __forceinline__ void ln_relu(float* buf,
                                        const float* __restrict__ g,
                                        const float* __restrict__ be, int tid) {
    const int s = tid >> 2, q = tid & 3;  // 4 threads per sample
    constexpr int SPAN = C / 4;
    float* row = buf + s * P + q * SPAN;
    float vals[SPAN];
    float sum = 0.0f;
#pragma unroll
    for (int j = 0; j < SPAN; ++j) { vals[j] = row[j]; sum += vals[j]; }
    sum += __shfl_xor_sync(0xffffffffu, sum, 1);
    sum += __shfl_xor_sync(0xffffffffu, sum, 2);
    const float mu = sum * (1.0f / C);
    float sq = 0.0f;
#pragma unroll
    for (int j = 0; j < SPAN; ++j) { float d = vals[j] - mu; sq += d * d; }
    sq += __shfl_xor_sync(0xffffffffu, sq, 1);
    sq += __shfl_xor_sync(0xffffffffu, sq, 2);
    const float inv = rsqrtf(sq * (1.0f / C) + 1e-5f);
#pragma unroll
    for (int j = 0; j < SPAN; ++j) {
        int jj = q * SPAN + j;
        float v = (vals[j] - mu) * inv * __ldg(g + jj) + __ldg(be + jj);
        row[j] = fmaxf(v, 0.0f);
    }
}

__global__ __launch_bounds__(128) void mlp_kernel(
    const float* __restrict__ xyz, const float* __restrict__ points,
    const float* __restrict__ new_xyz,
    const float* __restrict__ W1, const float* __restrict__ b1,
    const float* __restrict__ g1, const float* __restrict__ be1,
    const float* __restrict__ W2, const float* __restrict__ b2,
    const float* __restrict__ g2, const float* __restrict__ be2,
    const float* __restrict__ W3, const float* __restrict__ b3,
    const float* __restrict__ g3, const float* __restrict__ be3,
    float* __restrict__ new_points) {
    __shared__ float bufA[32 * PIN_A];
    __shared__ float bufB[32 * PIN_B];
    __shared__ int   sIdx[32];
    __shared__ float sCen[3];

    const int pair = blockIdx.x;        // b*1024 + s
    const int b    = pair >> 10;
    const int tid  = threadIdx.x;

    if (tid < 32) sIdx[tid] = g_group_idx[pair * NSAMPLE + tid];
    if (tid < 3)  sCen[tid] = new_xyz[(size_t)pair * 3 + tid];
    __syncthreads();

    // gather: 4 threads per sample; 67 channels = [xyz-offset(3), points(64)]
    {
        const int k = tid >> 2, q = tid & 3;
        const int n = sIdx[k];
        const float4* prow = (const float4*)(points + ((size_t)b * NPTS + n) * 64) + q * 4;
        float* dst = bufA + k * PIN_A + 3 + q * 16;
#pragma unroll
        for (int v = 0; v < 4; ++v) {
            float4 f = __ldg(prow + v);
            dst[v * 4 + 0] = f.x;
            dst[v * 4 + 1] = f.y;
            dst[v * 4 + 2] = f.z;
            dst[v * 4 + 3] = f.w;
        }
        if (q == 0) {
            const float* xr = xyz + ((size_t)b * NPTS + n) * 3;
            bufA[k * PIN_A + 0] = xr[0] - sCen[0];
            bufA[k * PIN_A + 1] = xr[1] - sCen[1];
            bufA[k * PIN_A + 2] = xr[2] - sCen[2];
        }
    }
    __syncthreads();

    gemm_tile<67, 64, PIN_A, PIN_B>(bufA, W1, b1, bufB, tid);
    __syncthreads();
    ln_relu<64, PIN_B>(bufB, g1, be1, tid);
    __syncthreads();

    gemm_tile<64, 64, PIN_B, PIN_A>(bufB, W2, b2, bufA, tid);
    __syncthreads();
    ln_relu<64, PIN_A>(bufA, g2, be2, tid);
    __syncthreads();

    gemm_tile<64, 128, PIN_A, PIN_B>(bufA, W3, b3, bufB, tid);
    __syncthreads();
    ln_relu<128, PIN_B>(bufB, g3, be3, tid);
    __syncthreads();

    // max over the 32 group samples; relu outputs >= 0 so init 0 is exact
    {
        const int j = tid;
        float m = 0.0f;
#pragma unroll 8
        for (int k = 0; k < 32; ++k) m = fmaxf(m, bufB[k * PIN_B + j]);
        new_points[(size_t)pair * 128 + j] = m;
    }
}

// ---------------------------------------------------------------------------
extern "C" void kernel_launch(void* const* d_in, const int* in_sizes, int n_in,
                              void* d_out, int out_size) {
    (void)in_sizes; (void)n_in; (void)out_size;
    const float* xyz    = (const float*)d_in[0];
    const float* points = (const float*)d_in[1];
    const float* W1  = (const float*)d_in[2];
    const float* b1  = (const float*)d_in[3];
    const float* g1  = (const float*)d_in[4];
    const float* be1 = (const float*)d_in[5];
    const float* W2  = (const float*)d_in[6];
    const float* b2  = (const float*)d_in[7];
    const float* g2  = (const float*)d_in[8];
    const float* be2 = (const float*)d_in[9];
    const float* W3  = (const float*)d_in[10];
    const float* b3  = (const float*)d_in[11];
    const float* g3  = (const float*)d_in[12];
    const float* be3 = (const float*)d_in[13];

    float* out        = (float*)d_out;
    float* new_xyz    = out;                          // [8,1024,3]
    float* new_points = out + BATCH * NPOINTS * 3;    // [8,1024,128]

    fps_kernel<<<BATCH, 256>>>(xyz, new_xyz);
    ball_kernel<<<dim3(NPOINTS / 8, BATCH), 256, NPTS * 3 * sizeof(float)>>>(xyz, new_xyz);
    mlp_kernel<<<BATCH * NPOINTS, 128>>>(xyz, points, new_xyz,
                                         W1, b1, g1, be1,
                                         W2, b2, g2, be2,
                                         W3, b3, g3, be3,
                                         new_points);
}